// round 9
// baseline (speedup 1.0000x reference)
#include <cuda_runtime.h>

#define TPB    256
#define QPB    512          // queries per block (2 per thread)
#define PAIRS  512          // candidate pairs per smem tile (1024 candidates)
#define GPAIRS 32           // pairs per group (rescan granule)
#define NGRP   (PAIRS / GPAIRS)

// ---------------- static scratch (no allocations) ----------------------------
__device__ float4             g_gxy[16384];   // gt  pairs: (x0,x1,y0,y1)
__device__ float4             g_gzw[16384];   // gt  pairs: (z0,z1,w0,w1)
__device__ float4             g_pxy[4096];    // pred pairs
__device__ float4             g_pzw[4096];
__device__ unsigned long long g_best1[8192];  // per pred: key | gt idx
__device__ unsigned long long g_best2[32768]; // per gt:   key | pred idx
__device__ float              g_partial[256];

// ---------------- packed f32x2 helpers ---------------------------------------
__device__ __forceinline__ unsigned long long splat2(float f) {
    unsigned long long r;
    asm("mov.b64 %0, {%1, %1};" : "=l"(r) : "f"(f));
    return r;
}
__device__ __forceinline__ unsigned long long ffma2(unsigned long long a,
                                                    unsigned long long b,
                                                    unsigned long long c) {
    unsigned long long d;
    asm("fma.rn.f32x2 %0, %1, %2, %3;" : "=l"(d) : "l"(a), "l"(b), "l"(c));
    return d;
}
__device__ __forceinline__ void unpack2(unsigned long long v, float& lo, float& hi) {
    asm("mov.b64 {%0, %1}, %2;" : "=f"(lo), "=f"(hi) : "l"(v));
}
// monotone float -> sortable unsigned (handles negatives)
__device__ __forceinline__ unsigned fkey(float f) {
    unsigned u = __float_as_uint(f);
    return u ^ ((unsigned)((int)u >> 31) | 0x80000000u);
}

// ---------------- prep: paired-SoA pack + winner init ------------------------
__global__ void prep_kernel(const float* __restrict__ pp,
                            const float* __restrict__ gp, int N, int M) {
    int i = blockIdx.x * blockDim.x + threadIdx.x;
    if (i < N) g_best1[i] = ~0ULL;
    if (i < M) g_best2[i] = ~0ULL;
    if (i < N / 2) {
        float x0 = pp[6*i],   y0 = pp[6*i+1], z0 = pp[6*i+2];
        float x1 = pp[6*i+3], y1 = pp[6*i+4], z1 = pp[6*i+5];
        g_pxy[i] = make_float4(x0, x1, y0, y1);
        g_pzw[i] = make_float4(z0, z1, x0*x0 + y0*y0 + z0*z0,
                                       x1*x1 + y1*y1 + z1*z1);
    }
    if (i < M / 2) {
        float x0 = gp[6*i],   y0 = gp[6*i+1], z0 = gp[6*i+2];
        float x1 = gp[6*i+3], y1 = gp[6*i+4], z1 = gp[6*i+5];
        g_gxy[i] = make_float4(x0, x1, y0, y1);
        g_gzw[i] = make_float4(z0, z1, x0*x0 + y0*y0 + z0*z0,
                                       x1*x1 + y1*y1 + z1*z1);
    }
}

// ---------------- NN argmin: min-only pass + group rescan --------------------
// score(q, c) = |c|^2 - 2 q.c   (same chain as validated rounds)
// DIR==0: queries = pred, candidates = gt  -> g_best1
// DIR==1: queries = gt,   candidates = pred -> g_best2
template <int DIR>
__global__ __launch_bounds__(TPB, 3) void nn_kernel(const float* __restrict__ qp) {
    __shared__ ulonglong2 sxy[PAIRS];   // (x0,x1) | (y0,y1)
    __shared__ ulonglong2 szw[PAIRS];   // (z0,z1) | (w0,w1)
    const ulonglong2* gxy = DIR ? (const ulonglong2*)g_pxy : (const ulonglong2*)g_gxy;
    const ulonglong2* gzw = DIR ? (const ulonglong2*)g_pzw : (const ulonglong2*)g_gzw;
    unsigned long long* best = DIR ? g_best2 : g_best1;

    const int pairbase = blockIdx.y * PAIRS;
    for (int t = threadIdx.x; t < PAIRS; t += TPB) {
        sxy[t] = gxy[pairbase + t];
        szw[t] = gzw[pairbase + t];
    }
    __syncthreads();

    const int qA = blockIdx.x * QPB + threadIdx.x;
    const int qB = qA + TPB;
    const unsigned long long Ax = splat2(-2.0f * qp[3*qA]);
    const unsigned long long Ay = splat2(-2.0f * qp[3*qA+1]);
    const unsigned long long Az = splat2(-2.0f * qp[3*qA+2]);
    const unsigned long long Bx = splat2(-2.0f * qp[3*qB]);
    const unsigned long long By = splat2(-2.0f * qp[3*qB+1]);
    const unsigned long long Bz = splat2(-2.0f * qp[3*qB+2]);

    // split accumulators (even/odd packed lane) -> two independent lat-4 chains
    float bmA0 = 3.4e38f, bmA1 = 3.4e38f, bmB0 = 3.4e38f, bmB1 = 3.4e38f;
    float bmA = 3.4e38f, bmB = 3.4e38f;
    int bgA = 0, bgB = 0;

    for (int g = 0; g < NGRP; g++) {
        const float oA = bmA, oB = bmB;
        const int t0 = g * GPAIRS;
#pragma unroll 8
        for (int t = t0; t < t0 + GPAIRS; t++) {
            ulonglong2 a = sxy[t];
            ulonglong2 b = szw[t];
            unsigned long long sA = ffma2(Ax, a.x, ffma2(Ay, a.y, ffma2(Az, b.x, b.y)));
            unsigned long long sB = ffma2(Bx, a.x, ffma2(By, a.y, ffma2(Bz, b.x, b.y)));
            float a0, a1, c0, c1;
            unpack2(sA, a0, a1);
            unpack2(sB, c0, c1);
            bmA0 = fminf(bmA0, a0);
            bmA1 = fminf(bmA1, a1);
            bmB0 = fminf(bmB0, c0);
            bmB1 = fminf(bmB1, c1);
        }
        bmA = fminf(bmA0, bmA1);
        bmB = fminf(bmB0, bmB1);
        bgA = (bmA < oA) ? g : bgA;   // first group achieving the final min wins
        bgB = (bmB < oB) ? g : bgB;   // (equal-later never strictly improves)
    }

    // rescan winning group only (32 pairs, uniform trip count, no divergence);
    // descending scan + odd-before-even overwrite => smallest matching index
    int iA = 0, iB = 0;
    {
        const int t0 = bgA * GPAIRS;
#pragma unroll
        for (int u = GPAIRS - 1; u >= 0; u--) {
            const int t = t0 + u;
            ulonglong2 a = sxy[t], b = szw[t];
            unsigned long long s = ffma2(Ax, a.x, ffma2(Ay, a.y, ffma2(Az, b.x, b.y)));
            float s0, s1; unpack2(s, s0, s1);
            iA = (s1 == bmA) ? 2*t + 1 : iA;
            iA = (s0 == bmA) ? 2*t     : iA;
        }
    }
    {
        const int t0 = bgB * GPAIRS;
#pragma unroll
        for (int u = GPAIRS - 1; u >= 0; u--) {
            const int t = t0 + u;
            ulonglong2 a = sxy[t], b = szw[t];
            unsigned long long s = ffma2(Bx, a.x, ffma2(By, a.y, ffma2(Bz, b.x, b.y)));
            float s0, s1; unpack2(s, s0, s1);
            iB = (s1 == bmB) ? 2*t + 1 : iB;
            iB = (s0 == bmB) ? 2*t     : iB;
        }
    }

    const int cbase = pairbase * 2;   // candidate index base of this tile
    atomicMin(&best[qA], ((unsigned long long)fkey(bmA) << 32) | (unsigned)(cbase + iA));
    atomicMin(&best[qB], ((unsigned long long)fkey(bmB) << 32) | (unsigned)(cbase + iB));
}

// ---------------- loss: deterministic two-stage reduction --------------------
__global__ __launch_bounds__(256) void loss_stage1(const float* __restrict__ pn,
                                                   const float* __restrict__ gn,
                                                   int N, int M) {
    const int tid = threadIdx.x;
    const int gid = blockIdx.x * blockDim.x + tid;
    const int stride = gridDim.x * blockDim.x;
    float s1 = 0.f, s2 = 0.f;
    for (int i = gid; i < N; i += stride) {
        int j = (int)(unsigned)g_best1[i];
        s1 += pn[3*i] * gn[3*j] + pn[3*i+1] * gn[3*j+1] + pn[3*i+2] * gn[3*j+2];
    }
    for (int j = gid; j < M; j += stride) {
        int i = (int)(unsigned)g_best2[j];
        s2 += gn[3*j] * pn[3*i] + gn[3*j+1] * pn[3*i+1] + gn[3*j+2] * pn[3*i+2];
    }
    __shared__ float r1[256], r2[256];
    r1[tid] = s1; r2[tid] = s2;
    __syncthreads();
    for (int o = 128; o > 0; o >>= 1) {
        if (tid < o) { r1[tid] += r1[tid + o]; r2[tid] += r2[tid + o]; }
        __syncthreads();
    }
    if (tid == 0) { g_partial[blockIdx.x] = r1[0]; g_partial[128 + blockIdx.x] = r2[0]; }
}

__global__ void finish_kernel(float* __restrict__ out, float invN, float invM) {
    __shared__ float sa[128], sb[128];
    int t = threadIdx.x;
    sa[t] = g_partial[t];
    sb[t] = g_partial[128 + t];
    __syncthreads();
    for (int o = 64; o > 0; o >>= 1) {
        if (t < o) { sa[t] += sa[t + o]; sb[t] += sb[t + o]; }
        __syncthreads();
    }
    if (t == 0) out[0] = 2.0f - sa[0] * invN - sb[0] * invM;
}

// ---------------- launch -----------------------------------------------------
extern "C" void kernel_launch(void* const* d_in, const int* in_sizes, int n_in,
                              void* d_out, int out_size) {
    const float* pred_pts = (const float*)d_in[0];
    const float* pred_nrm = (const float*)d_in[1];
    const float* gt_pts   = (const float*)d_in[2];
    const float* gt_nrm   = (const float*)d_in[3];
    float* out = (float*)d_out;

    const int N = in_sizes[0] / 3;   // 8192
    const int M = in_sizes[2] / 3;   // 32768
    const int mx = (N > M) ? N : M;

    prep_kernel<<<(mx + 255) / 256, 256>>>(pred_pts, gt_pts, N, M);

    dim3 g1(N / QPB, M / (2 * PAIRS));   // 16 x 32
    nn_kernel<0><<<g1, TPB>>>(pred_pts);

    dim3 g2(M / QPB, N / (2 * PAIRS));   // 64 x 8
    nn_kernel<1><<<g2, TPB>>>(gt_pts);

    loss_stage1<<<128, 256>>>(pred_nrm, gt_nrm, N, M);
    finish_kernel<<<1, 128>>>(out, 1.0f / (float)N, 1.0f / (float)M);
}

// round 10
// speedup vs baseline: 1.2940x; 1.2940x over previous
#include <cuda_runtime.h>

#define TPB    128
#define QPT    4            // queries per thread
#define QPB    (TPB*QPT)    // 512 queries per block
#define PAIRS  1024         // candidate pairs per smem tile (2048 candidates)
#define GPAIRS 32           // pairs per group (rescan granule)
#define NGRP   (PAIRS / GPAIRS)

// ---------------- static scratch (no allocations) ----------------------------
__device__ float4             g_gxy[16384];   // gt  pairs: (x0,x1,y0,y1)
__device__ float4             g_gzw[16384];   // gt  pairs: (z0,z1,w0,w1)
__device__ float4             g_pxy[4096];    // pred pairs
__device__ float4             g_pzw[4096];
__device__ unsigned long long g_best1[8192];  // per pred: key | gt idx
__device__ unsigned long long g_best2[32768]; // per gt:   key | pred idx
__device__ float              g_partial[256];

// ---------------- packed f32x2 helpers ---------------------------------------
__device__ __forceinline__ unsigned long long splat2(float f) {
    unsigned long long r;
    asm("mov.b64 %0, {%1, %1};" : "=l"(r) : "f"(f));
    return r;
}
__device__ __forceinline__ unsigned long long ffma2(unsigned long long a,
                                                    unsigned long long b,
                                                    unsigned long long c) {
    unsigned long long d;
    asm("fma.rn.f32x2 %0, %1, %2, %3;" : "=l"(d) : "l"(a), "l"(b), "l"(c));
    return d;
}
__device__ __forceinline__ void unpack2(unsigned long long v, float& lo, float& hi) {
    asm("mov.b64 {%0, %1}, %2;" : "=f"(lo), "=f"(hi) : "l"(v));
}
// monotone float -> sortable unsigned (handles negatives)
__device__ __forceinline__ unsigned fkey(float f) {
    unsigned u = __float_as_uint(f);
    return u ^ ((unsigned)((int)u >> 31) | 0x80000000u);
}

// ---------------- prep (3 kernels so nn_kernel<0> is launch #4 for ncu) ------
__global__ void init_kernel(int N, int M) {
    int i = blockIdx.x * blockDim.x + threadIdx.x;
    if (i < N) g_best1[i] = ~0ULL;
    if (i < M) g_best2[i] = ~0ULL;
}
__global__ void pack_pred_kernel(const float* __restrict__ pp, int Nh) {
    int i = blockIdx.x * blockDim.x + threadIdx.x;
    if (i < Nh) {
        float x0 = pp[6*i],   y0 = pp[6*i+1], z0 = pp[6*i+2];
        float x1 = pp[6*i+3], y1 = pp[6*i+4], z1 = pp[6*i+5];
        g_pxy[i] = make_float4(x0, x1, y0, y1);
        g_pzw[i] = make_float4(z0, z1, x0*x0 + y0*y0 + z0*z0,
                                       x1*x1 + y1*y1 + z1*z1);
    }
}
__global__ void pack_gt_kernel(const float* __restrict__ gp, int Mh) {
    int i = blockIdx.x * blockDim.x + threadIdx.x;
    if (i < Mh) {
        float x0 = gp[6*i],   y0 = gp[6*i+1], z0 = gp[6*i+2];
        float x1 = gp[6*i+3], y1 = gp[6*i+4], z1 = gp[6*i+5];
        g_gxy[i] = make_float4(x0, x1, y0, y1);
        g_gzw[i] = make_float4(z0, z1, x0*x0 + y0*y0 + z0*z0,
                                       x1*x1 + y1*y1 + z1*z1);
    }
}

// ---------------- NN argmin: min-only pass + group rescan --------------------
// score(q, c) = |c|^2 - 2 q.c   (identical chain to validated rounds)
// DIR==0: queries = pred, candidates = gt  -> g_best1
// DIR==1: queries = gt,   candidates = pred -> g_best2
template <int DIR>
__global__ __launch_bounds__(TPB) void nn_kernel(const float* __restrict__ qp) {
    __shared__ ulonglong2 sxy[PAIRS];   // (x0,x1) | (y0,y1)
    __shared__ ulonglong2 szw[PAIRS];   // (z0,z1) | (w0,w1)
    const ulonglong2* gxy = DIR ? (const ulonglong2*)g_pxy : (const ulonglong2*)g_gxy;
    const ulonglong2* gzw = DIR ? (const ulonglong2*)g_pzw : (const ulonglong2*)g_gzw;
    unsigned long long* best = DIR ? g_best2 : g_best1;

    const int pairbase = blockIdx.y * PAIRS;
    for (int t = threadIdx.x; t < PAIRS; t += TPB) {
        sxy[t] = gxy[pairbase + t];
        szw[t] = gzw[pairbase + t];
    }
    __syncthreads();

    // 4 queries per thread
    int q[QPT];
    unsigned long long Qx[QPT], Qy[QPT], Qz[QPT];
#pragma unroll
    for (int k = 0; k < QPT; k++) {
        q[k]  = blockIdx.x * QPB + k * TPB + threadIdx.x;
        Qx[k] = splat2(-2.0f * qp[3*q[k]]);
        Qy[k] = splat2(-2.0f * qp[3*q[k]+1]);
        Qz[k] = splat2(-2.0f * qp[3*q[k]+2]);
    }

    // split accumulators: per query, per packed lane -> 8 independent chains
    float bm0[QPT], bm1[QPT], bm[QPT];
    int   bg[QPT];
#pragma unroll
    for (int k = 0; k < QPT; k++) {
        bm0[k] = 3.4e38f; bm1[k] = 3.4e38f; bm[k] = 3.4e38f; bg[k] = 0;
    }

    for (int g = 0; g < NGRP; g++) {
        float om[QPT];
#pragma unroll
        for (int k = 0; k < QPT; k++) om[k] = bm[k];
        const int t0 = g * GPAIRS;
#pragma unroll 8
        for (int t = t0; t < t0 + GPAIRS; t++) {
            ulonglong2 a = sxy[t];
            ulonglong2 b = szw[t];
#pragma unroll
            for (int k = 0; k < QPT; k++) {
                unsigned long long s =
                    ffma2(Qx[k], a.x, ffma2(Qy[k], a.y, ffma2(Qz[k], b.x, b.y)));
                float s0, s1; unpack2(s, s0, s1);
                bm0[k] = fminf(bm0[k], s0);
                bm1[k] = fminf(bm1[k], s1);
            }
        }
#pragma unroll
        for (int k = 0; k < QPT; k++) {
            bm[k] = fminf(bm0[k], bm1[k]);
            bg[k] = (bm[k] < om[k]) ? g : bg[k];  // strict-drop => first group
        }
    }

    // rescan winning group per query (32 pairs, uniform, no divergence);
    // descending scan + odd-before-even overwrite => smallest matching index
    const int cbase = pairbase * 2;
#pragma unroll
    for (int k = 0; k < QPT; k++) {
        int idx = 0;
        const int t0 = bg[k] * GPAIRS;
#pragma unroll
        for (int u = GPAIRS - 1; u >= 0; u--) {
            const int t = t0 + u;
            ulonglong2 a = sxy[t], b = szw[t];
            unsigned long long s =
                ffma2(Qx[k], a.x, ffma2(Qy[k], a.y, ffma2(Qz[k], b.x, b.y)));
            float s0, s1; unpack2(s, s0, s1);
            idx = (s1 == bm[k]) ? 2*t + 1 : idx;
            idx = (s0 == bm[k]) ? 2*t     : idx;
        }
        atomicMin(&best[q[k]],
                  ((unsigned long long)fkey(bm[k]) << 32) | (unsigned)(cbase + idx));
    }
}

// ---------------- loss: deterministic two-stage reduction --------------------
__global__ __launch_bounds__(256) void loss_stage1(const float* __restrict__ pn,
                                                   const float* __restrict__ gn,
                                                   int N, int M) {
    const int tid = threadIdx.x;
    const int gid = blockIdx.x * blockDim.x + tid;
    const int stride = gridDim.x * blockDim.x;
    float s1 = 0.f, s2 = 0.f;
    for (int i = gid; i < N; i += stride) {
        int j = (int)(unsigned)g_best1[i];
        s1 += pn[3*i] * gn[3*j] + pn[3*i+1] * gn[3*j+1] + pn[3*i+2] * gn[3*j+2];
    }
    for (int j = gid; j < M; j += stride) {
        int i = (int)(unsigned)g_best2[j];
        s2 += gn[3*j] * pn[3*i] + gn[3*j+1] * pn[3*i+1] + gn[3*j+2] * pn[3*i+2];
    }
    __shared__ float r1[256], r2[256];
    r1[tid] = s1; r2[tid] = s2;
    __syncthreads();
    for (int o = 128; o > 0; o >>= 1) {
        if (tid < o) { r1[tid] += r1[tid + o]; r2[tid] += r2[tid + o]; }
        __syncthreads();
    }
    if (tid == 0) { g_partial[blockIdx.x] = r1[0]; g_partial[128 + blockIdx.x] = r2[0]; }
}

__global__ void finish_kernel(float* __restrict__ out, float invN, float invM) {
    __shared__ float sa[128], sb[128];
    int t = threadIdx.x;
    sa[t] = g_partial[t];
    sb[t] = g_partial[128 + t];
    __syncthreads();
    for (int o = 64; o > 0; o >>= 1) {
        if (t < o) { sa[t] += sa[t + o]; sb[t] += sb[t + o]; }
        __syncthreads();
    }
    if (t == 0) out[0] = 2.0f - sa[0] * invN - sb[0] * invM;
}

// ---------------- launch -----------------------------------------------------
extern "C" void kernel_launch(void* const* d_in, const int* in_sizes, int n_in,
                              void* d_out, int out_size) {
    const float* pred_pts = (const float*)d_in[0];
    const float* pred_nrm = (const float*)d_in[1];
    const float* gt_pts   = (const float*)d_in[2];
    const float* gt_nrm   = (const float*)d_in[3];
    float* out = (float*)d_out;

    const int N = in_sizes[0] / 3;   // 8192
    const int M = in_sizes[2] / 3;   // 32768

    init_kernel<<<(M + 255) / 256, 256>>>(N, M);                 // launch 1
    pack_pred_kernel<<<(N/2 + 255) / 256, 256>>>(pred_pts, N/2); // launch 2
    pack_gt_kernel<<<(M/2 + 255) / 256, 256>>>(gt_pts, M/2);     // launch 3

    dim3 g1(N / QPB, M / (2 * PAIRS));   // 16 x 16   (launch 4 -> ncu target)
    nn_kernel<0><<<g1, TPB>>>(pred_pts);

    dim3 g2(M / QPB, N / (2 * PAIRS));   // 64 x 4
    nn_kernel<1><<<g2, TPB>>>(gt_pts);

    loss_stage1<<<128, 256>>>(pred_nrm, gt_nrm, N, M);
    finish_kernel<<<1, 128>>>(out, 1.0f / (float)N, 1.0f / (float)M);
}